// round 14
// baseline (speedup 1.0000x reference)
#include <cuda_runtime.h>
#include <cuda_fp16.h>
#include <stdint.h>

#define NN 50000
#define NE 800000
#define IN_DIM 64
#define HEADS 4
#define HEAD_DIM 64
#define OUT_DIM 256
#define NEG_SLOPE 0.2f
#define EPSV 1e-16f
#define CAP 96            // fixed bucket capacity; P(deg>96)≈e^-70 for Poisson(16)

typedef unsigned long long ull;

// ---------------- scratch (static device globals; no allocations) ----------
__device__ __align__(16) __half g_h2[(size_t)NN * OUT_DIM];  // fp16 projected features
__device__ __align__(16) float  g_asrc[NN * HEADS];
__device__ __align__(16) float  g_adst[NN * HEADS];
__device__ int   g_cnt[NN];                 // per-node fill counters
__device__ __align__(16) int g_colp[(size_t)NN * CAP];  // bucketed incoming-src lists
__device__ int   g_is64;

__device__ __forceinline__ float lrelu(float v) {
    return v > 0.f ? v : NEG_SLOPE * v;
}

// packed fp32x2 FMA: d = a*b + d
__device__ __forceinline__ void ffma2(ull& d, ull a, ull b) {
    asm("fma.rn.f32x2 %0, %1, %2, %0;" : "+l"(d) : "l"(a), "l"(b));
}
__device__ __forceinline__ ull pack_dup(float v) {
    ull r; unsigned int u = __float_as_uint(v);
    asm("mov.b64 %0, {%1, %1};" : "=l"(r) : "r"(u));
    return r;
}
__device__ __forceinline__ float2 unpack2(ull v) {
    float lo, hi;
    asm("mov.b64 {%0, %1}, %2;" : "=f"(lo), "=f"(hi) : "l"(v));
    return make_float2(lo, hi);
}

__device__ __forceinline__ int load_edge(const void* ei, size_t pos, int is64) {
    if (is64) return (int)((const long long*)ei)[pos];
    return ((const int*)ei)[pos];
}

// ---------------- K0: probe edge dtype + zero counters ----------------------
__global__ void init_kernel(const void* ei, int n_nodes) {
    int i = blockIdx.x * blockDim.x + threadIdx.x;
    if (i < n_nodes) g_cnt[i] = 0;
    if (i == 0) {
        const long long* p = (const long long*)ei;
        int ok = 1;
        for (int k = 0; k < 64; k++) {
            long long v = p[k];
            if (v < 0 || v >= (long long)n_nodes) ok = 0;
        }
        g_is64 = ok;
    }
}

// ---------------- K1: scatter edges into fixed buckets ----------------------
__global__ void scatter_kernel(const void* __restrict__ ei, int E, int n_nodes) {
    int e = blockIdx.x * blockDim.x + threadIdx.x;
    if (e < E) {
        int is64 = g_is64;
        int src = load_edge(ei, e, is64);
        int dst = load_edge(ei, (size_t)E + e, is64);
        if (src >= 0 && src < n_nodes && dst >= 0 && dst < n_nodes) {
            int c = atomicAdd(&g_cnt[dst], 1);
            if (c < CAP) g_colp[(size_t)dst * CAP + c] = src;
        }
    }
}

// ---------------- K2: h = x @ W via packed FFMA2, 8 nodes/warp-iter ---------
// No __launch_bounds__: needs ~120-130 regs (acc2 = 64 regs) -- a 128-reg cap
// would force spills (the R11 failure). ptxas free choice => no spill.
__global__ void gemm_kernel(const float* __restrict__ x,
                            const float* __restrict__ W,
                            const float* __restrict__ att_src,
                            const float* __restrict__ att_dst,
                            int n_nodes) {
    const int tid    = threadIdx.x;
    const int lane   = tid & 31;
    const int warp   = tid >> 5;
    const int gw     = blockIdx.x * (blockDim.x >> 5) + warp;
    const int nwarps = gridDim.x * (blockDim.x >> 5);
    const int head   = lane >> 3;
    const int dcol   = (lane & 7) * 8;

    float as8[8], ad8[8];
#pragma unroll
    for (int c = 0; c < 8; c++) {
        as8[c] = __ldg(att_src + head * HEAD_DIM + dcol + c);
        ad8[c] = __ldg(att_dst + head * HEAD_DIM + dcol + c);
    }

    for (int nb = gw * 8; nb < n_nodes; nb += nwarps * 8) {
        float2 xv[8];
#pragma unroll
        for (int j = 0; j < 8; j++) {
            int n = nb + j;
            if (n < n_nodes)
                xv[j] = __ldg((const float2*)(x + (size_t)n * IN_DIM + lane * 2));
            else { xv[j].x = 0.f; xv[j].y = 0.f; }
        }

        ull acc2[8][4];
#pragma unroll
        for (int j = 0; j < 8; j++)
#pragma unroll
            for (int c = 0; c < 4; c++) acc2[j][c] = 0ull;

#pragma unroll 2
        for (int k = 0; k < IN_DIM; k++) {
            ulonglong2 wa = __ldg((const ulonglong2*)(W + (size_t)k * OUT_DIM + lane * 8));
            ulonglong2 wb = __ldg((const ulonglong2*)(W + (size_t)k * OUT_DIM + lane * 8 + 4));
#pragma unroll
            for (int j = 0; j < 8; j++) {
                float xk = __shfl_sync(0xffffffffu, (k & 1) ? xv[j].y : xv[j].x, k >> 1);
                ull xk2 = pack_dup(xk);
                ffma2(acc2[j][0], xk2, wa.x);
                ffma2(acc2[j][1], xk2, wa.y);
                ffma2(acc2[j][2], xk2, wb.x);
                ffma2(acc2[j][3], xk2, wb.y);
            }
        }

#pragma unroll
        for (int j = 0; j < 8; j++) {
            int n = nb + j;
            if (n < n_nodes) {
                float2 f0 = unpack2(acc2[j][0]);
                float2 f1 = unpack2(acc2[j][1]);
                float2 f2 = unpack2(acc2[j][2]);
                float2 f3 = unpack2(acc2[j][3]);

                __half2 hh[4];
                hh[0] = __float22half2_rn(f0);
                hh[1] = __float22half2_rn(f1);
                hh[2] = __float22half2_rn(f2);
                hh[3] = __float22half2_rn(f3);
                *(uint4*)(g_h2 + (size_t)n * OUT_DIM + lane * 8) = *(uint4*)hh;

                float av[8] = {f0.x, f0.y, f1.x, f1.y, f2.x, f2.y, f3.x, f3.y};
                float ps = 0.f, pd = 0.f;
#pragma unroll
                for (int c = 0; c < 8; c++) {
                    ps = fmaf(av[c], as8[c], ps);
                    pd = fmaf(av[c], ad8[c], pd);
                }
#pragma unroll
                for (int off = 4; off >= 1; off >>= 1) {
                    ps += __shfl_xor_sync(0xffffffffu, ps, off);
                    pd += __shfl_xor_sync(0xffffffffu, pd, off);
                }
                if ((lane & 7) == 0) {
                    g_asrc[n * HEADS + head] = ps;
                    g_adst[n * HEADS + head] = pd;
                }
            }
        }
    }
}

// ---------------- K3: single-pass softmax + aggregation (fp16 gather) -------
__global__ void __launch_bounds__(256) aggr_kernel(const float* __restrict__ bias,
                                                   float* __restrict__ out, int n_nodes) {
    int gw   = (blockIdx.x * blockDim.x + threadIdx.x) >> 5;
    int lane = threadIdx.x & 31;
    if (gw >= n_nodes) return;
    const int i    = gw;
    int deg = g_cnt[i];
    if (deg > CAP) deg = CAP;
    const int rs   = i * CAP;
    const int re   = rs + deg;
    const int head = lane >> 3;

    const float adh = g_adst[i * 4 + head];
    const float ash = g_asrc[i * 4 + head];

    float acc[8];
    float denom;
    // self-loop (fp16 row, same precision as all other messages)
    {
        float es = __expf(lrelu(ash + adh));
        denom = es;
        uint4 r = *(const uint4*)(g_h2 + (size_t)i * OUT_DIM + lane * 8);
        const __half2* q = (const __half2*)&r;
#pragma unroll
        for (int c = 0; c < 4; c++) {
            float2 f = __half22float2(q[c]);
            acc[c*2]   = es * f.x;
            acc[c*2+1] = es * f.y;
        }
    }

    int e = rs;
    // 4-wide: one int4 index load + 4 a-gathers + 4 row-gathers in flight
    for (; e + 4 <= re; e += 4) {
        int4 sv = *(const int4*)(g_colp + e);
        float a0 = g_asrc[sv.x * 4 + head];
        float a1 = g_asrc[sv.y * 4 + head];
        float a2 = g_asrc[sv.z * 4 + head];
        float a3 = g_asrc[sv.w * 4 + head];
        uint4 r0 = *(const uint4*)(g_h2 + (size_t)sv.x * OUT_DIM + lane * 8);
        uint4 r1 = *(const uint4*)(g_h2 + (size_t)sv.y * OUT_DIM + lane * 8);
        uint4 r2 = *(const uint4*)(g_h2 + (size_t)sv.z * OUT_DIM + lane * 8);
        uint4 r3 = *(const uint4*)(g_h2 + (size_t)sv.w * OUT_DIM + lane * 8);
        float al0 = __expf(lrelu(a0 + adh));
        float al1 = __expf(lrelu(a1 + adh));
        float al2 = __expf(lrelu(a2 + adh));
        float al3 = __expf(lrelu(a3 + adh));
        denom += (al0 + al1) + (al2 + al3);

        const __half2* q0 = (const __half2*)&r0;
        const __half2* q1 = (const __half2*)&r1;
        const __half2* q2 = (const __half2*)&r2;
        const __half2* q3 = (const __half2*)&r3;
#pragma unroll
        for (int c = 0; c < 4; c++) {
            float2 f0 = __half22float2(q0[c]);
            float2 f1 = __half22float2(q1[c]);
            float2 f2 = __half22float2(q2[c]);
            float2 f3 = __half22float2(q3[c]);
            acc[c*2]   = fmaf(al0, f0.x, acc[c*2]);
            acc[c*2+1] = fmaf(al0, f0.y, acc[c*2+1]);
            acc[c*2]   = fmaf(al1, f1.x, acc[c*2]);
            acc[c*2+1] = fmaf(al1, f1.y, acc[c*2+1]);
            acc[c*2]   = fmaf(al2, f2.x, acc[c*2]);
            acc[c*2+1] = fmaf(al2, f2.y, acc[c*2+1]);
            acc[c*2]   = fmaf(al3, f3.x, acc[c*2]);
            acc[c*2+1] = fmaf(al3, f3.y, acc[c*2+1]);
        }
    }
    for (; e < re; ++e) {
        int s = g_colp[e];
        float a = g_asrc[s * 4 + head];
        uint4 r = *(const uint4*)(g_h2 + (size_t)s * OUT_DIM + lane * 8);
        float al = __expf(lrelu(a + adh));
        denom += al;
        const __half2* q = (const __half2*)&r;
#pragma unroll
        for (int c = 0; c < 4; c++) {
            float2 f = __half22float2(q[c]);
            acc[c*2]   = fmaf(al, f.x, acc[c*2]);
            acc[c*2+1] = fmaf(al, f.y, acc[c*2+1]);
        }
    }

    const float invd = 1.f / (denom + EPSV);
    float b[8];
#pragma unroll
    for (int c = 0; c < 8; c++) b[c] = bias[lane * 8 + c];
    float4 o0 = make_float4(fmaf(acc[0], invd, b[0]), fmaf(acc[1], invd, b[1]),
                            fmaf(acc[2], invd, b[2]), fmaf(acc[3], invd, b[3]));
    float4 o1 = make_float4(fmaf(acc[4], invd, b[4]), fmaf(acc[5], invd, b[5]),
                            fmaf(acc[6], invd, b[6]), fmaf(acc[7], invd, b[7]));
    *(float4*)(out + (size_t)i * OUT_DIM + lane * 8)     = o0;
    *(float4*)(out + (size_t)i * OUT_DIM + lane * 8 + 4) = o1;
}

// ---------------- launch: bucket scatter forked onto a 2nd stream -----------
extern "C" void kernel_launch(void* const* d_in, const int* in_sizes, int n_in,
                              void* d_out, int out_size) {
    const float* x       = (const float*)d_in[0];
    const void*  ei      = d_in[1];
    const float* W       = (const float*)d_in[2];
    const float* att_src = (const float*)d_in[3];
    const float* att_dst = (const float*)d_in[4];
    const float* bias    = (const float*)d_in[5];
    float*       out     = (float*)d_out;

    const int N = in_sizes[0] / IN_DIM;       // 50000
    const int E = in_sizes[1] / 2;            // 800000

    static cudaStream_t s2 = nullptr;
    static cudaEvent_t evFork = nullptr, evJoin = nullptr;
    if (s2 == nullptr) {
        cudaStreamCreateWithFlags(&s2, cudaStreamNonBlocking);
        cudaEventCreateWithFlags(&evFork, cudaEventDisableTiming);
        cudaEventCreateWithFlags(&evJoin, cudaEventDisableTiming);
    }

    cudaEventRecord(evFork, 0);
    cudaStreamWaitEvent(s2, evFork, 0);

    init_kernel<<<(N + 255) / 256, 256, 0, s2>>>(ei, N);
    scatter_kernel<<<(E + 255) / 256, 256, 0, s2>>>(ei, E, N);

    gemm_kernel<<<296, 256>>>(x, W, att_src, att_dst, N);

    cudaEventRecord(evJoin, s2);
    cudaStreamWaitEvent(0, evJoin, 0);

    const int total_threads = N * 32;
    aggr_kernel<<<(total_threads + 255) / 256, 256>>>(bias, out, N);
}

// round 15
// speedup vs baseline: 1.2943x; 1.2943x over previous
#include <cuda_runtime.h>
#include <cuda_fp16.h>
#include <stdint.h>

#define NN 50000
#define NE 800000
#define IN_DIM 64
#define HEADS 4
#define HEAD_DIM 64
#define OUT_DIM 256
#define NEG_SLOPE 0.2f
#define EPSV 1e-16f
#define CAP 96            // fixed bucket capacity; P(deg>96)≈e^-70 for Poisson(16)

typedef unsigned long long ull;

// ---------------- scratch (static device globals; no allocations) ----------
__device__ __align__(16) __half g_h2[(size_t)NN * OUT_DIM];  // fp16 projected features
__device__ __align__(16) float  g_asrc[NN * HEADS];
__device__ __align__(16) float  g_adst[NN * HEADS];
__device__ int   g_cnt[NN];                 // per-node fill counters
__device__ __align__(16) int g_colp[(size_t)NN * CAP];  // bucketed incoming-src lists
__device__ int   g_is64;

__device__ __forceinline__ float lrelu(float v) {
    return v > 0.f ? v : NEG_SLOPE * v;
}

// packed fp32x2 FMA: d = a*b + d
__device__ __forceinline__ void ffma2(ull& d, ull a, ull b) {
    asm("fma.rn.f32x2 %0, %1, %2, %0;" : "+l"(d) : "l"(a), "l"(b));
}
__device__ __forceinline__ ull pack_dup(float v) {
    ull r; unsigned int u = __float_as_uint(v);
    asm("mov.b64 %0, {%1, %1};" : "=l"(r) : "r"(u));
    return r;
}
__device__ __forceinline__ float2 unpack2(ull v) {
    float lo, hi;
    asm("mov.b64 {%0, %1}, %2;" : "=f"(lo), "=f"(hi) : "l"(v));
    return make_float2(lo, hi);
}

__device__ __forceinline__ int load_edge(const void* ei, size_t pos, int is64) {
    if (is64) return (int)((const long long*)ei)[pos];
    return ((const int*)ei)[pos];
}

// ---------------- K0: probe edge dtype + zero counters ----------------------
__global__ void init_kernel(const void* ei, int n_nodes) {
    int i = blockIdx.x * blockDim.x + threadIdx.x;
    if (i < n_nodes) g_cnt[i] = 0;
    if (i == 0) {
        const long long* p = (const long long*)ei;
        int ok = 1;
        for (int k = 0; k < 64; k++) {
            long long v = p[k];
            if (v < 0 || v >= (long long)n_nodes) ok = 0;
        }
        g_is64 = ok;
    }
}

// ---------------- K1: scatter edges into fixed buckets ----------------------
__global__ void scatter_kernel(const void* __restrict__ ei, int E, int n_nodes) {
    int e = blockIdx.x * blockDim.x + threadIdx.x;
    if (e < E) {
        int is64 = g_is64;
        int src = load_edge(ei, e, is64);
        int dst = load_edge(ei, (size_t)E + e, is64);
        if (src >= 0 && src < n_nodes && dst >= 0 && dst < n_nodes) {
            int c = atomicAdd(&g_cnt[dst], 1);
            if (c < CAP) g_colp[(size_t)dst * CAP + c] = src;
        }
    }
}

// ---------------- K2: h = x @ W via packed FFMA2, 4 nodes/warp-iter ---------
__global__ void gemm_kernel(const float* __restrict__ x,
                            const float* __restrict__ W,
                            const float* __restrict__ att_src,
                            const float* __restrict__ att_dst,
                            int n_nodes) {
    const int tid    = threadIdx.x;
    const int lane   = tid & 31;
    const int warp   = tid >> 5;
    const int gw     = blockIdx.x * (blockDim.x >> 5) + warp;
    const int nwarps = gridDim.x * (blockDim.x >> 5);
    const int head   = lane >> 3;
    const int dcol   = (lane & 7) * 8;

    float as8[8], ad8[8];
#pragma unroll
    for (int c = 0; c < 8; c++) {
        as8[c] = __ldg(att_src + head * HEAD_DIM + dcol + c);
        ad8[c] = __ldg(att_dst + head * HEAD_DIM + dcol + c);
    }

    for (int nb = gw * 4; nb < n_nodes; nb += nwarps * 4) {
        float2 xv[4];
#pragma unroll
        for (int j = 0; j < 4; j++) {
            int n = nb + j;
            if (n < n_nodes)
                xv[j] = __ldg((const float2*)(x + (size_t)n * IN_DIM + lane * 2));
            else { xv[j].x = 0.f; xv[j].y = 0.f; }
        }

        ull acc2[4][4];
#pragma unroll
        for (int j = 0; j < 4; j++)
#pragma unroll
            for (int c = 0; c < 4; c++) acc2[j][c] = 0ull;

#pragma unroll 4
        for (int k = 0; k < IN_DIM; k++) {
            ulonglong2 wa = __ldg((const ulonglong2*)(W + (size_t)k * OUT_DIM + lane * 8));
            ulonglong2 wb = __ldg((const ulonglong2*)(W + (size_t)k * OUT_DIM + lane * 8 + 4));
#pragma unroll
            for (int j = 0; j < 4; j++) {
                float xk = __shfl_sync(0xffffffffu, (k & 1) ? xv[j].y : xv[j].x, k >> 1);
                ull xk2 = pack_dup(xk);
                ffma2(acc2[j][0], xk2, wa.x);
                ffma2(acc2[j][1], xk2, wa.y);
                ffma2(acc2[j][2], xk2, wb.x);
                ffma2(acc2[j][3], xk2, wb.y);
            }
        }

#pragma unroll
        for (int j = 0; j < 4; j++) {
            int n = nb + j;
            if (n < n_nodes) {
                float2 f0 = unpack2(acc2[j][0]);
                float2 f1 = unpack2(acc2[j][1]);
                float2 f2 = unpack2(acc2[j][2]);
                float2 f3 = unpack2(acc2[j][3]);

                __half2 hh[4];
                hh[0] = __float22half2_rn(f0);
                hh[1] = __float22half2_rn(f1);
                hh[2] = __float22half2_rn(f2);
                hh[3] = __float22half2_rn(f3);
                *(uint4*)(g_h2 + (size_t)n * OUT_DIM + lane * 8) = *(uint4*)hh;

                float av[8] = {f0.x, f0.y, f1.x, f1.y, f2.x, f2.y, f3.x, f3.y};
                float ps = 0.f, pd = 0.f;
#pragma unroll
                for (int c = 0; c < 8; c++) {
                    ps = fmaf(av[c], as8[c], ps);
                    pd = fmaf(av[c], ad8[c], pd);
                }
#pragma unroll
                for (int off = 4; off >= 1; off >>= 1) {
                    ps += __shfl_xor_sync(0xffffffffu, ps, off);
                    pd += __shfl_xor_sync(0xffffffffu, pd, off);
                }
                if ((lane & 7) == 0) {
                    g_asrc[n * HEADS + head] = ps;
                    g_adst[n * HEADS + head] = pd;
                }
            }
        }
    }
}

// ---------------- K3: single-pass softmax + aggregation (fp16 gather) -------
__global__ void __launch_bounds__(128) aggr_kernel(const float* __restrict__ bias,
                                                   float* __restrict__ out, int n_nodes) {
    int gw   = (blockIdx.x * blockDim.x + threadIdx.x) >> 5;
    int lane = threadIdx.x & 31;
    if (gw >= n_nodes) return;
    const int i    = gw;
    int deg = g_cnt[i];
    if (deg > CAP) deg = CAP;
    const int rs   = i * CAP;
    const int re   = rs + deg;
    const int head = lane >> 3;

    const float adh = g_adst[i * 4 + head];
    const float ash = g_asrc[i * 4 + head];

    float acc[8];
    float denom;
    // self-loop (fp16 row, same precision as all other messages)
    {
        float es = __expf(lrelu(ash + adh));
        denom = es;
        uint4 r = *(const uint4*)(g_h2 + (size_t)i * OUT_DIM + lane * 8);
        const __half2* q = (const __half2*)&r;
#pragma unroll
        for (int c = 0; c < 4; c++) {
            float2 f = __half22float2(q[c]);
            acc[c*2]   = es * f.x;
            acc[c*2+1] = es * f.y;
        }
    }

    int e = rs;
    // 4-wide: one int4 index load + 4 a-gathers + 4 row-gathers in flight
    for (; e + 4 <= re; e += 4) {
        int4 sv = *(const int4*)(g_colp + e);
        float a0 = g_asrc[sv.x * 4 + head];
        float a1 = g_asrc[sv.y * 4 + head];
        float a2 = g_asrc[sv.z * 4 + head];
        float a3 = g_asrc[sv.w * 4 + head];
        uint4 r0 = *(const uint4*)(g_h2 + (size_t)sv.x * OUT_DIM + lane * 8);
        uint4 r1 = *(const uint4*)(g_h2 + (size_t)sv.y * OUT_DIM + lane * 8);
        uint4 r2 = *(const uint4*)(g_h2 + (size_t)sv.z * OUT_DIM + lane * 8);
        uint4 r3 = *(const uint4*)(g_h2 + (size_t)sv.w * OUT_DIM + lane * 8);
        float al0 = __expf(lrelu(a0 + adh));
        float al1 = __expf(lrelu(a1 + adh));
        float al2 = __expf(lrelu(a2 + adh));
        float al3 = __expf(lrelu(a3 + adh));
        denom += (al0 + al1) + (al2 + al3);

        const __half2* q0 = (const __half2*)&r0;
        const __half2* q1 = (const __half2*)&r1;
        const __half2* q2 = (const __half2*)&r2;
        const __half2* q3 = (const __half2*)&r3;
#pragma unroll
        for (int c = 0; c < 4; c++) {
            float2 f0 = __half22float2(q0[c]);
            float2 f1 = __half22float2(q1[c]);
            float2 f2 = __half22float2(q2[c]);
            float2 f3 = __half22float2(q3[c]);
            acc[c*2]   = fmaf(al0, f0.x, acc[c*2]);
            acc[c*2+1] = fmaf(al0, f0.y, acc[c*2+1]);
            acc[c*2]   = fmaf(al1, f1.x, acc[c*2]);
            acc[c*2+1] = fmaf(al1, f1.y, acc[c*2+1]);
            acc[c*2]   = fmaf(al2, f2.x, acc[c*2]);
            acc[c*2+1] = fmaf(al2, f2.y, acc[c*2+1]);
            acc[c*2]   = fmaf(al3, f3.x, acc[c*2]);
            acc[c*2+1] = fmaf(al3, f3.y, acc[c*2+1]);
        }
    }
    for (; e < re; ++e) {
        int s = g_colp[e];
        float a = g_asrc[s * 4 + head];
        uint4 r = *(const uint4*)(g_h2 + (size_t)s * OUT_DIM + lane * 8);
        float al = __expf(lrelu(a + adh));
        denom += al;
        const __half2* q = (const __half2*)&r;
#pragma unroll
        for (int c = 0; c < 4; c++) {
            float2 f = __half22float2(q[c]);
            acc[c*2]   = fmaf(al, f.x, acc[c*2]);
            acc[c*2+1] = fmaf(al, f.y, acc[c*2+1]);
        }
    }

    const float invd = 1.f / (denom + EPSV);
    float b[8];
#pragma unroll
    for (int c = 0; c < 8; c++) b[c] = bias[lane * 8 + c];
    float4 o0 = make_float4(fmaf(acc[0], invd, b[0]), fmaf(acc[1], invd, b[1]),
                            fmaf(acc[2], invd, b[2]), fmaf(acc[3], invd, b[3]));
    float4 o1 = make_float4(fmaf(acc[4], invd, b[4]), fmaf(acc[5], invd, b[5]),
                            fmaf(acc[6], invd, b[6]), fmaf(acc[7], invd, b[7]));
    *(float4*)(out + (size_t)i * OUT_DIM + lane * 8)     = o0;
    *(float4*)(out + (size_t)i * OUT_DIM + lane * 8 + 4) = o1;
}

// ---------------- launch: bucket scatter forked onto a 2nd stream -----------
extern "C" void kernel_launch(void* const* d_in, const int* in_sizes, int n_in,
                              void* d_out, int out_size) {
    const float* x       = (const float*)d_in[0];
    const void*  ei      = d_in[1];
    const float* W       = (const float*)d_in[2];
    const float* att_src = (const float*)d_in[3];
    const float* att_dst = (const float*)d_in[4];
    const float* bias    = (const float*)d_in[5];
    float*       out     = (float*)d_out;

    const int N = in_sizes[0] / IN_DIM;       // 50000
    const int E = in_sizes[1] / 2;            // 800000

    static cudaStream_t s2 = nullptr;
    static cudaEvent_t evFork = nullptr, evJoin = nullptr;
    if (s2 == nullptr) {
        cudaStreamCreateWithFlags(&s2, cudaStreamNonBlocking);
        cudaEventCreateWithFlags(&evFork, cudaEventDisableTiming);
        cudaEventCreateWithFlags(&evJoin, cudaEventDisableTiming);
    }

    cudaEventRecord(evFork, 0);
    cudaStreamWaitEvent(s2, evFork, 0);

    init_kernel<<<(N + 255) / 256, 256, 0, s2>>>(ei, N);
    scatter_kernel<<<(E + 255) / 256, 256, 0, s2>>>(ei, E, N);

    gemm_kernel<<<592, 256>>>(x, W, att_src, att_dst, N);

    cudaEventRecord(evJoin, s2);
    cudaStreamWaitEvent(0, evJoin, 0);

    const int total_threads = N * 32;
    aggr_kernel<<<(total_threads + 127) / 128, 128>>>(bias, out, N);
}